// round 17
// baseline (speedup 1.0000x reference)
#include <cuda_runtime.h>
#include <cuda_bf16.h>
#include <cstdint>

// B=128, N=512, diagonals k=0..509 (offset k+1), len(k)=511-k.
// out = (loss[B], loss[B]).
//
// TMA-staged streaming: CTA (b, s) owns rows p ≡ s (mod 4) (strips are
// byte-identical -> perfect balance). Tile = 8 such rows; each row's tail
// cols [(p+1)&~3, 512) is staged smem-ward by ONE cp.async.bulk (TMA engine:
// deep HW queue, bypasses the per-SM L1tex in-flight cap that pinned every
// LDG/LDGSTS variant at ~3.6 TB/s). 3-stage mbarrier ring, 2 tiles in
// flight. Thread k owns diagonal k: reads buf[rr*W + k+s+32j+4rr+1];
// consecutive threads -> consecutive smem addresses (conflict-free).
#define NN   512
#define W    516        // padded smem row stride (2064 B, 16B multiple)
#define KD   510
#define TPB  512
#define RSG  4          // strips per batch (rows interleaved mod 4)
#define SUB  8          // rows per tile
#define NT   16         // tiles per strip
#define NSTG 3          // ring stages
#define MAXB 256

__device__ float2 g_part[MAXB * RSG * 512];
__device__ int    g_count[MAXB];     // zero-init; reset by last CTA each replay

#define MB_WAIT(mb, ph)                                                        \
    asm volatile("{\n\t.reg .pred P1;\n"                                       \
                 "W_%=:\n\t"                                                   \
                 "mbarrier.try_wait.parity.acquire.cta.shared::cta.b64 "       \
                 "P1, [%0], %1;\n\t"                                           \
                 "@P1 bra.uni D_%=;\n\t"                                       \
                 "bra.uni W_%=;\n"                                             \
                 "D_%=:\n\t}" :: "r"(mb), "r"(ph) : "memory")

__global__ __launch_bounds__(TPB, 4)
void diag_tma(const float* __restrict__ S, float* __restrict__ out,
              int B, int out_size) {
    __shared__ __align__(16) float buf[NSTG * SUB * W];     // 49.5 KB ring
    __shared__ __align__(8) unsigned long long mbar[NSTG];
    const int b   = blockIdx.x;
    const int s   = blockIdx.y;
    const int tid = threadIdx.x;
    const int k   = tid;            // diagonal owned (k<510 valid)

    const float* __restrict__ M = S + (size_t)b * NN * NN;
    const uint32_t sbase = (uint32_t)__cvta_generic_to_shared(buf);
    const uint32_t mb0   = (uint32_t)__cvta_generic_to_shared(mbar);

    if (tid == 0) {
        #pragma unroll
        for (int i = 0; i < NSTG; ++i)
            asm volatile("mbarrier.init.shared.b64 [%0], 1;"
                         :: "r"(mb0 + 8u * i) : "memory");
        asm volatile("fence.proxy.async.shared::cta;" ::: "memory");
    }
    __syncthreads();

    // ---- stage tile j (rows p = s + 32j + 4r, r=0..7) via 8 bulk copies
    auto issue = [&](int j) {
        const int slot = j % NSTG;
        const uint32_t mb  = mb0 + 8u * slot;
        const uint32_t sb  = sbase + (uint32_t)(slot * SUB * W) * 4u;
        int tx = 0;
        #pragma unroll
        for (int r = 0; r < SUB; ++r) {
            const int p  = s + 32 * j + 4 * r;
            const int c0 = (p + 1) & ~3;
            tx += (NN - c0) * 4;
        }
        asm volatile("mbarrier.arrive.expect_tx.shared.b64 _, [%0], %1;"
                     :: "r"(mb), "r"(tx) : "memory");
        #pragma unroll
        for (int r = 0; r < SUB; ++r) {
            const int p  = s + 32 * j + 4 * r;
            const int c0 = (p + 1) & ~3;
            const int bytes = (NN - c0) * 4;
            const uint32_t dst = sb + (uint32_t)(r * W + c0) * 4u;
            const float* src = M + (size_t)p * NN + c0;
            asm volatile(
                "cp.async.bulk.shared::cta.global.mbarrier::complete_tx::bytes"
                " [%0], [%1], %2, [%3];"
                :: "r"(dst), "l"(src), "r"(bytes), "r"(mb) : "memory");
        }
    };

    if (tid == 0) { issue(0); issue(1); }

    float sk = 0.f, qk = 0.f;

    for (int j = 0; j < NT; ++j) {
        if (tid == 0 && j + 2 < NT) issue(j + 2);   // slot (j-1)%3: freed at j-1

        MB_WAIT(mb0 + 8u * (j % NSTG), (j / NSTG) & 1);

        const float* tb = buf + (j % NSTG) * SUB * W;
        const int cbase = k + s + 32 * j + 1;       // col on diag k at row r=0
        #pragma unroll
        for (int rr = 0; rr < SUB; ++rr) {
            const int c = cbase + 4 * rr;
            if (c < NN) {
                float x = tb[rr * W + c];
                sk += x; qk = fmaf(x, x, qk);
            }
        }
        __syncthreads();                            // release ring slot
    }

    // ---- per-(strip,diag) partial
    if (k < KD)
        g_part[(b * RSG + s) * 512 + k] = make_float2(sk, qk);
    __threadfence();
    __syncthreads();

    __shared__ int is_last;
    if (tid == 0) {
        int old = atomicAdd(&g_count[b], 1);
        is_last = (old == RSG - 1);
        if (old == RSG - 1) g_count[b] = 0;         // reset for next replay
    }
    __syncthreads();

    if (is_last) {
        float contrib = 0.f;
        if (k < KD) {
            float Ss = 0.f, Qs = 0.f;
            #pragma unroll
            for (int i = 0; i < RSG; ++i) {         // fixed order: deterministic
                float2 v = g_part[(b * RSG + i) * 512 + k];
                Ss += v.x; Qs += v.y;
            }
            const float len = 511.0f - (float)k;
            float mean = Ss / len;
            float var  = fmaxf((Qs - Ss * mean) / (len - 1.0f), 0.0f);
            contrib = sqrtf(var) * len * 0.2f;
        }
        __shared__ float red[TPB];
        red[tid] = contrib;
        __syncthreads();
        #pragma unroll
        for (int st = TPB / 2; st >= 32; st >>= 1) {
            if (tid < st) red[tid] += red[tid + st];
            __syncthreads();
        }
        if (tid < 32) {
            float v = red[tid];
            #pragma unroll
            for (int off = 16; off > 0; off >>= 1)
                v += __shfl_down_sync(0xFFFFFFFFu, v, off);
            if (tid == 0) {
                float loss = v / (float)KD;
                out[b] = loss;
                if (out_size >= 2 * B) out[B + b] = loss;
            }
        }
    }
}

extern "C" void kernel_launch(void* const* d_in, const int* in_sizes, int n_in,
                              void* d_out, int out_size) {
    const float* S = (const float*)d_in[0];
    float* out = (float*)d_out;
    const int B = in_sizes[0] / (NN * NN);
    dim3 grid(B, RSG);
    diag_tma<<<grid, TPB>>>(S, out, B, out_size);
}